// round 15
// baseline (speedup 1.0000x reference)
#include <cuda_runtime.h>

// ---------------------------------------------------------------------------
// GNN: ln -> GAT0 -> lrelu -> GAT1 -> ln+res -> lrelu -> edge MLP -> out
// Final attention: softmax over [E,1] == 1.0  =>  out = 2*eo + edge_attr
//
// Round 15: merged pre+scatter launch (g_cnt is reset by k_edge_out of the
// PREVIOUS call — device globals start zeroed, so the invariant holds on
// every call/replay), SW=4 aggregation for deeper load pipelining.
// ---------------------------------------------------------------------------

static constexpr int   NN  = 100000;   // nodes
static constexpr int   NE  = 3200000;  // edges
static constexpr int   F   = 9;
static constexpr int   FP  = 12;       // padded row: 3 x float4
static constexpr int   CAP = 96;       // per-node bucket capacity (max deg ~70)
static constexpr int   SWA = 4;        // lanes per node in agg kernels
static constexpr int   SWE = 8;        // lanes per node in edge head
static constexpr float EPS = 1e-5f;
static constexpr int   TPB = 256;

static constexpr int NBN  = (NN + TPB - 1) / TPB;          // 391 node blocks
static constexpr int NBE2 = (NE / 2 + TPB - 1) / TPB;      // 6250 scatter blocks

// Scratch (device globals; no allocation allowed). g_cnt starts zeroed at
// module load and is re-zeroed by k_edge_out at the end of every call.
__device__ __align__(16) float g_xpA[NN * FP];   // layer0 proj: [xv9, ss, dd, -]
__device__ __align__(16) float g_xpB[NN * FP];   // layer1 proj: [xv9, ss, dd, lattr]
__device__ __align__(16) float g_agg[NN * FP];   // [acc9, wsum, easum, -]
__device__ __align__(16) float g_h1 [NN * FP];   // residual
__device__ __align__(16) float g_us [NN * FP];   // [us9, sum, sumsq, -]
__device__ __align__(16) float g_ud [NN * FP];   // [ud9, sum, sumsq, -]
__device__ int  g_cnt[NN];                       // bucket cursor == in-degree
__device__ __align__(16) int4 g_bkt[(size_t)NN * CAP];  // (src, ea, eix, 0)

__device__ __forceinline__ float lrelu(float v, float s) {
    return fmaxf(v, s * v);
}

// --- 1. Merged: [blocks 0..NBN) LayerNorm+W0 -> xpA ; [NBN..) scatter ------
__global__ void k_pre_scatter(const float* __restrict__ x,
                              const float* __restrict__ g, const float* __restrict__ b,
                              const float* __restrict__ W0,
                              const float* __restrict__ as0, const float* __restrict__ ad0,
                              const int* __restrict__ src, const int* __restrict__ dst,
                              const float* __restrict__ ea) {
    int t = threadIdx.x;
    if (blockIdx.x < NBN) {
        // ---- node part: LN + W0 projection ----
        __shared__ float sW[F * F];
        __shared__ float sa[2 * F];
        if (t < F * F) sW[t] = W0[t];
        if (t < F)          sa[t] = as0[t];
        else if (t < 2 * F) sa[t] = ad0[t - F];
        __syncthreads();

        int i = blockIdx.x * TPB + t;
        if (i >= NN) return;

        float v[F], m = 0.f;
#pragma unroll
        for (int k = 0; k < F; k++) { v[k] = x[i * F + k]; m += v[k]; }
        m *= (1.f / F);
        float var = 0.f;
#pragma unroll
        for (int k = 0; k < F; k++) { float d = v[k] - m; var += d * d; }
        var *= (1.f / F);
        float r = rsqrtf(var + EPS);
        float hv[F];
#pragma unroll
        for (int k = 0; k < F; k++)
            hv[k] = (v[k] - m) * r * __ldg(&g[k]) + __ldg(&b[k]);

        float xv[F], ss = 0.f, dd = 0.f;
#pragma unroll
        for (int j = 0; j < F; j++) {
            float a = 0.f;
#pragma unroll
            for (int k = 0; k < F; k++) a += hv[k] * sW[k * F + j];
            xv[j] = a;
            ss += a * sa[j];
            dd += a * sa[F + j];
        }
        float4* xr = reinterpret_cast<float4*>(g_xpA + (size_t)i * FP);
        xr[0] = make_float4(xv[0], xv[1], xv[2], xv[3]);
        xr[1] = make_float4(xv[4], xv[5], xv[6], xv[7]);
        xr[2] = make_float4(xv[8], ss, dd, 0.f);
    } else {
        // ---- scatter part: build dst-grouped buckets (cnt pre-zeroed) ----
        int base = 2 * ((blockIdx.x - NBN) * TPB + t);
        if (base >= NE) return;
        int2   s2 = *reinterpret_cast<const int2*>(src + base);
        int2   d2 = *reinterpret_cast<const int2*>(dst + base);
        float2 a2 = *reinterpret_cast<const float2*>(ea + base);
        int p0 = atomicAdd(&g_cnt[d2.x], 1);
        g_bkt[(size_t)d2.x * CAP + p0] = make_int4(s2.x, __float_as_int(a2.x), base, 0);
        int p1 = atomicAdd(&g_cnt[d2.y], 1);
        g_bkt[(size_t)d2.y * CAP + p1] = make_int4(s2.y, __float_as_int(a2.y), base + 1, 0);
    }
}

// --- 2. GAT aggregation: sub-warp(4) per dst node, pure gather --------------
template <bool L0>
__global__ void k_agg(const float* __restrict__ We, const float* __restrict__ ae) {
    __shared__ float s_ce;
    if (threadIdx.x == 0) {
        float c = 0.f;
#pragma unroll
        for (int j = 0; j < F; j++) c += We[j] * ae[j];
        s_ce = c;
    }
    __syncthreads();

    int gsw  = (blockIdx.x * blockDim.x + threadIdx.x) / SWA;
    int lane = threadIdx.x & (SWA - 1);
    bool live = (gsw < NN);
    int n = live ? gsw : (NN - 1);        // clamp: keep full warp for shuffles
    int cnt = g_cnt[n];
    const float* __restrict__ xp = L0 ? g_xpA : g_xpB;
    float dd_n = __ldg(&xp[(size_t)n * FP + 10]);
    float ce = s_ce;

    float acc[F] = {0.f, 0.f, 0.f, 0.f, 0.f, 0.f, 0.f, 0.f, 0.f};
    float wsum = 0.f, easum = 0.f;
    const int4* bucket = g_bkt + (size_t)n * CAP;
    for (int k = lane; k < cnt; k += SWA) {
        int4 e = __ldg(&bucket[k]);
        float ea_ = __int_as_float(e.y);
        const float4* xr = reinterpret_cast<const float4*>(xp + (size_t)e.x * FP);
        float4 p0 = __ldg(xr), p1 = __ldg(xr + 1), p2 = __ldg(xr + 2);
        float w = __expf(lrelu(p2.y + dd_n + ea_ * ce, 0.2f));
        acc[0] = fmaf(w, p0.x, acc[0]); acc[1] = fmaf(w, p0.y, acc[1]);
        acc[2] = fmaf(w, p0.z, acc[2]); acc[3] = fmaf(w, p0.w, acc[3]);
        acc[4] = fmaf(w, p1.x, acc[4]); acc[5] = fmaf(w, p1.y, acc[5]);
        acc[6] = fmaf(w, p1.z, acc[6]); acc[7] = fmaf(w, p1.w, acc[7]);
        acc[8] = fmaf(w, p2.x, acc[8]);
        wsum += w;
        if (L0) easum += ea_;
    }
    // reduce across the 4-lane sub-warp (xor stays within the group)
#pragma unroll
    for (int o = SWA / 2; o > 0; o >>= 1) {
#pragma unroll
        for (int j = 0; j < F; j++) acc[j] += __shfl_xor_sync(0xFFFFFFFFu, acc[j], o);
        wsum += __shfl_xor_sync(0xFFFFFFFFu, wsum, o);
        if (L0) easum += __shfl_xor_sync(0xFFFFFFFFu, easum, o);
    }
    if (live && lane == 0) {
        float4* ar = reinterpret_cast<float4*>(g_agg + (size_t)n * FP);
        ar[0] = make_float4(acc[0], acc[1], acc[2], acc[3]);
        ar[1] = make_float4(acc[4], acc[5], acc[6], acc[7]);
        ar[2] = make_float4(acc[8], wsum, L0 ? easum : 0.f, 0.f);
    }
}

// --- 3. Finish layer 0 (THREAD per node): self-loop + normalize + b0 +
//        lrelu -> h1; project with W1 -> xpB (carries lattr in slot 11). ----
__global__ void k_fin0(const float* __restrict__ b0,
                       const float* __restrict__ W1,
                       const float* __restrict__ as1, const float* __restrict__ ad1,
                       const float* __restrict__ We0, const float* __restrict__ ae0) {
    __shared__ float sW[F * F];
    __shared__ float sa[2 * F];
    __shared__ float sb[F];
    __shared__ float s_ce;
    int t = threadIdx.x;
    if (t < F * F) sW[t] = W1[t];
    if (t < F) { sa[t] = as1[t]; sb[t] = b0[t]; }
    else if (t < 2 * F) sa[t] = ad1[t - F];
    if (t == 0) {
        float c = 0.f;
#pragma unroll
        for (int j = 0; j < F; j++) c += We0[j] * ae0[j];
        s_ce = c;
    }
    __syncthreads();

    int i = blockIdx.x * blockDim.x + t;
    if (i >= NN) return;

    const float4* ar = reinterpret_cast<const float4*>(g_agg + (size_t)i * FP);
    float4 a0 = ar[0], a1 = ar[1], a2 = ar[2];       // (acc8, wsum, easum, -)
    const float4* pr = reinterpret_cast<const float4*>(g_xpA + (size_t)i * FP);
    float4 p0 = pr[0], p1 = pr[1], p2 = pr[2];       // (xv8, ss, dd, -)
    float acc[F] = {a0.x, a0.y, a0.z, a0.w, a1.x, a1.y, a1.z, a1.w, a2.x};
    float xvn[F] = {p0.x, p0.y, p0.z, p0.w, p1.x, p1.y, p1.z, p1.w, p2.x};
    float deg   = (float)g_cnt[i];
    float lattr = a2.z / fmaxf(deg, 1.f);
    float wself = __expf(lrelu(p2.y + p2.z + lattr * s_ce, 0.2f));
    float inv = 1.f / (a2.y + wself + 1e-16f);
    float hv[F];
#pragma unroll
    for (int k = 0; k < F; k++)
        hv[k] = lrelu(fmaf(wself, xvn[k], acc[k]) * inv + sb[k], 0.01f);
    float4* hr = reinterpret_cast<float4*>(g_h1 + (size_t)i * FP);
    hr[0] = make_float4(hv[0], hv[1], hv[2], hv[3]);
    hr[1] = make_float4(hv[4], hv[5], hv[6], hv[7]);
    hr[2] = make_float4(hv[8], 0.f, 0.f, 0.f);

    float xv[F], ss = 0.f, dd = 0.f;
#pragma unroll
    for (int j = 0; j < F; j++) {
        float a = 0.f;
#pragma unroll
        for (int k = 0; k < F; k++) a += hv[k] * sW[k * F + j];
        xv[j] = a;
        ss += a * sa[j];
        dd += a * sa[F + j];
    }
    float4* xr = reinterpret_cast<float4*>(g_xpB + (size_t)i * FP);
    xr[0] = make_float4(xv[0], xv[1], xv[2], xv[3]);
    xr[1] = make_float4(xv[4], xv[5], xv[6], xv[7]);
    xr[2] = make_float4(xv[8], ss, dd, lattr);
}

// --- 4. Finish layer 1 (THREAD per node): self-loop + normalize + LN +
//        residual + lrelu; precompute edge-head halves us/ud + stats. -------
__global__ void k_post1(const float* __restrict__ b,
                        const float* __restrict__ ng, const float* __restrict__ nb,
                        const float* __restrict__ We1, const float* __restrict__ ae1,
                        const float* __restrict__ g2,
                        const float* __restrict__ etW) {
    __shared__ float sGw[2 * F * F];   // g2[k] * etW[k*F+j]
    __shared__ float s_ce;
    int t = threadIdx.x;
    if (t < 2 * F * F) sGw[t] = g2[t / F] * etW[t];
    if (t == 0) {
        float c = 0.f;
#pragma unroll
        for (int j = 0; j < F; j++) c += We1[j] * ae1[j];
        s_ce = c;
    }
    __syncthreads();

    int i = blockIdx.x * blockDim.x + t;
    if (i >= NN) return;

    const float4* ar = reinterpret_cast<const float4*>(g_agg + (size_t)i * FP);
    float4 a0 = ar[0], a1 = ar[1], a2 = ar[2];       // (acc8, wsum, -, -)
    const float4* pr = reinterpret_cast<const float4*>(g_xpB + (size_t)i * FP);
    float4 p0 = pr[0], p1 = pr[1], p2 = pr[2];       // (xv8, ss, dd, lattr)
    float acc[F] = {a0.x, a0.y, a0.z, a0.w, a1.x, a1.y, a1.z, a1.w, a2.x};
    float xvn[F] = {p0.x, p0.y, p0.z, p0.w, p1.x, p1.y, p1.z, p1.w, p2.x};
    float wself = __expf(lrelu(p2.y + p2.z + p2.w * s_ce, 0.2f));
    float inv = 1.f / (a2.y + wself + 1e-16f);

    float v[F], m = 0.f;
#pragma unroll
    for (int j = 0; j < F; j++) {
        v[j] = fmaf(wself, xvn[j], acc[j]) * inv + b[j];
        m += v[j];
    }
    m *= (1.f / F);
    float var = 0.f;
#pragma unroll
    for (int j = 0; j < F; j++) { float d = v[j] - m; var += d * d; }
    var *= (1.f / F);
    float r = rsqrtf(var + EPS);

    const float4* hr = reinterpret_cast<const float4*>(g_h1 + (size_t)i * FP);
    float4 h0v = hr[0], h1v = hr[1], h2v = hr[2];
    float h1a[F] = {h0v.x, h0v.y, h0v.z, h0v.w, h1v.x, h1v.y, h1v.z, h1v.w, h2v.x};

    float o[F], sum = 0.f, sq = 0.f;
#pragma unroll
    for (int j = 0; j < F; j++) {
        o[j] = lrelu((v[j] - m) * r * ng[j] + nb[j] + h1a[j], 0.01f);
        sum += o[j];
        sq  += o[j] * o[j];
    }

    float us[F], ud[F];
#pragma unroll
    for (int j = 0; j < F; j++) {
        float a = 0.f, bb = 0.f;
#pragma unroll
        for (int k = 0; k < F; k++) {
            a  += o[k] * sGw[k * F + j];
            bb += o[k] * sGw[(F + k) * F + j];
        }
        us[j] = a; ud[j] = bb;
    }
    float4* ur = reinterpret_cast<float4*>(g_us + (size_t)i * FP);
    ur[0] = make_float4(us[0], us[1], us[2], us[3]);
    ur[1] = make_float4(us[4], us[5], us[6], us[7]);
    ur[2] = make_float4(us[8], sum, sq, 0.f);
    float4* vr = reinterpret_cast<float4*>(g_ud + (size_t)i * FP);
    vr[0] = make_float4(ud[0], ud[1], ud[2], ud[3]);
    vr[1] = make_float4(ud[4], ud[5], ud[6], ud[7]);
    vr[2] = make_float4(ud[8], sum, sq, 0.f);
}

// --- 5. Edge head: sub-warp(8) per node; resets g_cnt for the next call ----
__global__ void k_edge_out(const float* __restrict__ g2, const float* __restrict__ b2,
                           const float* __restrict__ etW, const float* __restrict__ etb,
                           const float* __restrict__ fcW, const float* __restrict__ fcb,
                           float* __restrict__ out) {
    __shared__ float sCs[F], sCb[F], sFc[F], sFcb;
    int t = threadIdx.x;
    if (t < F) {
        float cs = 0.f, cb = etb[t];
#pragma unroll
        for (int k = 0; k < 2 * F; k++) {
            cs += g2[k] * etW[k * F + t];
            cb += b2[k] * etW[k * F + t];
        }
        sCs[t] = cs; sCb[t] = cb; sFc[t] = fcW[t];
    }
    if (t == F) sFcb = fcb[0];
    __syncthreads();

    int gsw  = (blockIdx.x * blockDim.x + t) / SWE;
    int lane = t & (SWE - 1);
    if (gsw >= NN) return;                // grid exact: never taken
    int n   = gsw;
    int cnt = g_cnt[n];

    const float4* vr = reinterpret_cast<const float4*>(g_ud + (size_t)n * FP);
    float4 v0 = __ldg(vr), v1 = __ldg(vr + 1), v2 = __ldg(vr + 2);

    const int4* bucket = g_bkt + (size_t)n * CAP;
    for (int k = lane; k < cnt; k += SWE) {
        int4 e = __ldg(&bucket[k]);
        float ea = __int_as_float(e.y);
        const float4* ur = reinterpret_cast<const float4*>(g_us + (size_t)e.x * FP);
        float4 u0 = __ldg(ur), u1 = __ldg(ur + 1), u2 = __ldg(ur + 2);

        float m   = (u2.y + v2.y) * (1.f / (2 * F));
        float var = fmaf(-m, m, (u2.z + v2.z) * (1.f / (2 * F)));
        float r   = rsqrtf(var + EPS);
        float u[F] = {u0.x + v0.x, u0.y + v0.y, u0.z + v0.z, u0.w + v0.w,
                      u1.x + v1.x, u1.y + v1.y, u1.z + v1.z, u1.w + v1.w,
                      u2.x + v2.x};
        float eo = sFcb;
#pragma unroll
        for (int j = 0; j < F; j++) {
            float acc = fmaf(r, fmaf(-m, sCs[j], u[j]), sCb[j]);
            eo = fmaf(lrelu(acc, 0.01f), sFc[j], eo);
        }
        out[e.z] = fmaf(2.f, eo, ea);
    }
    // reset for the next kernel_launch call (only this sub-warp uses cnt[n])
    if (lane == 0) g_cnt[n] = 0;
}

// ---------------------------------------------------------------------------
extern "C" void kernel_launch(void* const* d_in, const int* in_sizes, int n_in,
                              void* d_out, int out_size) {
    const float* x     = (const float*)d_in[0];
    const int*   ei    = (const int*)  d_in[1];
    const float* ea    = (const float*)d_in[2];
    const float* ln1_g = (const float*)d_in[3];
    const float* ln1_b = (const float*)d_in[4];
    const float* W0    = (const float*)d_in[5];
    const float* as0   = (const float*)d_in[6];
    const float* ad0   = (const float*)d_in[7];
    const float* We0   = (const float*)d_in[8];
    const float* ae0   = (const float*)d_in[9];
    const float* b0    = (const float*)d_in[10];
    const float* W1    = (const float*)d_in[11];
    const float* as1   = (const float*)d_in[12];
    const float* ad1   = (const float*)d_in[13];
    const float* We1   = (const float*)d_in[14];
    const float* ae1   = (const float*)d_in[15];
    const float* b1    = (const float*)d_in[16];
    const float* ng1   = (const float*)d_in[17];
    const float* nb1   = (const float*)d_in[18];
    const float* ln2_g = (const float*)d_in[19];
    const float* ln2_b = (const float*)d_in[20];
    const float* et_W  = (const float*)d_in[21];
    const float* et_b  = (const float*)d_in[22];
    const float* fc_W  = (const float*)d_in[23];
    const float* fc_b  = (const float*)d_in[24];
    // att_W / att_b are provably dead (softmax over a single element)

    const int* src = ei;
    const int* dst = ei + NE;
    float* out = (float*)d_out;

    int nbMerged = NBN + NBE2;
    int nbN   = NBN;
    int nbAgg = (int)(((size_t)NN * SWA + TPB - 1) / TPB);
    int nbEo  = (int)(((size_t)NN * SWE + TPB - 1) / TPB);

    k_pre_scatter<<<nbMerged, TPB>>>(x, ln1_g, ln1_b, W0, as0, ad0, src, dst, ea);

    k_agg<true><<<nbAgg, TPB>>>(We0, ae0);                  // GAT layer 0
    k_fin0<<<nbN, TPB>>>(b0, W1, as1, ad1, We0, ae0);

    k_agg<false><<<nbAgg, TPB>>>(We1, ae1);                 // GAT layer 1
    k_post1<<<nbN, TPB>>>(b1, ng1, nb1, We1, ae1, ln2_g, et_W);

    k_edge_out<<<nbEo, TPB>>>(ln2_g, ln2_b, et_W, et_b, fc_W, fc_b, out);
}

// round 16
// speedup vs baseline: 1.0189x; 1.0189x over previous
#include <cuda_runtime.h>

// ---------------------------------------------------------------------------
// GNN: ln -> GAT0 -> lrelu -> GAT1 -> ln+res -> lrelu -> edge MLP -> out
// Final attention: softmax over [E,1] == 1.0  =>  out = 2*eo + edge_attr
//
// Round 16: round-14 launch structure (separate pre/scatter; epilogues are
// thread-per-node) with sub-warp-4 gather kernels everywhere.
// ---------------------------------------------------------------------------

static constexpr int   NN  = 100000;   // nodes
static constexpr int   NE  = 3200000;  // edges
static constexpr int   F   = 9;
static constexpr int   FP  = 12;       // padded row: 3 x float4
static constexpr int   CAP = 96;       // per-node bucket capacity (max deg ~70)
static constexpr int   SWA = 4;        // lanes per node in agg kernels
static constexpr int   SWE = 4;        // lanes per node in edge head
static constexpr float EPS = 1e-5f;
static constexpr int   TPB = 256;

// Scratch (device globals; no allocation allowed)
__device__ __align__(16) float g_xpA[NN * FP];   // layer0 proj: [xv9, ss, dd, -]
__device__ __align__(16) float g_xpB[NN * FP];   // layer1 proj: [xv9, ss, dd, lattr]
__device__ __align__(16) float g_agg[NN * FP];   // [acc9, wsum, easum, -]
__device__ __align__(16) float g_h1 [NN * FP];   // residual
__device__ __align__(16) float g_us [NN * FP];   // [us9, sum, sumsq, -]
__device__ __align__(16) float g_ud [NN * FP];   // [ud9, sum, sumsq, -]
__device__ int  g_cnt[NN];                       // bucket cursor == in-degree
__device__ __align__(16) int4 g_bkt[(size_t)NN * CAP];  // (src, ea, eix, 0)

__device__ __forceinline__ float lrelu(float v, float s) {
    return fmaxf(v, s * v);
}

// --- 1. LayerNorm x + W0 projection -> xpA; zero cursors -------------------
__global__ void k_pre(const float* __restrict__ x,
                      const float* __restrict__ g, const float* __restrict__ b,
                      const float* __restrict__ W0,
                      const float* __restrict__ as0, const float* __restrict__ ad0) {
    __shared__ float sW[F * F];
    __shared__ float sa[2 * F];
    int t = threadIdx.x;
    if (t < F * F) sW[t] = W0[t];
    if (t < F)          sa[t] = as0[t];
    else if (t < 2 * F) sa[t] = ad0[t - F];
    __syncthreads();

    int i = blockIdx.x * blockDim.x + t;
    if (i >= NN) return;

    float v[F], m = 0.f;
#pragma unroll
    for (int k = 0; k < F; k++) { v[k] = x[i * F + k]; m += v[k]; }
    m *= (1.f / F);
    float var = 0.f;
#pragma unroll
    for (int k = 0; k < F; k++) { float d = v[k] - m; var += d * d; }
    var *= (1.f / F);
    float r = rsqrtf(var + EPS);
    float hv[F];
#pragma unroll
    for (int k = 0; k < F; k++) hv[k] = (v[k] - m) * r * __ldg(&g[k]) + __ldg(&b[k]);

    float xv[F], ss = 0.f, dd = 0.f;
#pragma unroll
    for (int j = 0; j < F; j++) {
        float a = 0.f;
#pragma unroll
        for (int k = 0; k < F; k++) a += hv[k] * sW[k * F + j];
        xv[j] = a;
        ss += a * sa[j];
        dd += a * sa[F + j];
    }
    float4* xr = reinterpret_cast<float4*>(g_xpA + (size_t)i * FP);
    xr[0] = make_float4(xv[0], xv[1], xv[2], xv[3]);
    xr[1] = make_float4(xv[4], xv[5], xv[6], xv[7]);
    xr[2] = make_float4(xv[8], ss, dd, 0.f);
    g_cnt[i] = 0;
}

// --- 2. Build dst-grouped buckets: one 16B store per edge -------------------
__global__ void k_scatter(const int* __restrict__ src, const int* __restrict__ dst,
                          const float* __restrict__ ea) {
    int base = 2 * (blockIdx.x * blockDim.x + threadIdx.x);
    if (base >= NE) return;
    int2   s2 = *reinterpret_cast<const int2*>(src + base);
    int2   d2 = *reinterpret_cast<const int2*>(dst + base);
    float2 a2 = *reinterpret_cast<const float2*>(ea + base);
    int p0 = atomicAdd(&g_cnt[d2.x], 1);
    g_bkt[(size_t)d2.x * CAP + p0] = make_int4(s2.x, __float_as_int(a2.x), base, 0);
    int p1 = atomicAdd(&g_cnt[d2.y], 1);
    g_bkt[(size_t)d2.y * CAP + p1] = make_int4(s2.y, __float_as_int(a2.y), base + 1, 0);
}

// --- 3. GAT aggregation: sub-warp(4) per dst node, pure gather --------------
template <bool L0>
__global__ void k_agg(const float* __restrict__ We, const float* __restrict__ ae) {
    __shared__ float s_ce;
    if (threadIdx.x == 0) {
        float c = 0.f;
#pragma unroll
        for (int j = 0; j < F; j++) c += We[j] * ae[j];
        s_ce = c;
    }
    __syncthreads();

    int gsw  = (blockIdx.x * blockDim.x + threadIdx.x) / SWA;
    int lane = threadIdx.x & (SWA - 1);
    bool live = (gsw < NN);
    int n = live ? gsw : (NN - 1);        // clamp: keep full warp for shuffles
    int cnt = g_cnt[n];
    const float* __restrict__ xp = L0 ? g_xpA : g_xpB;
    float dd_n = __ldg(&xp[(size_t)n * FP + 10]);
    float ce = s_ce;

    float acc[F] = {0.f, 0.f, 0.f, 0.f, 0.f, 0.f, 0.f, 0.f, 0.f};
    float wsum = 0.f, easum = 0.f;
    const int4* bucket = g_bkt + (size_t)n * CAP;
    for (int k = lane; k < cnt; k += SWA) {
        int4 e = __ldg(&bucket[k]);
        float ea_ = __int_as_float(e.y);
        const float4* xr = reinterpret_cast<const float4*>(xp + (size_t)e.x * FP);
        float4 p0 = __ldg(xr), p1 = __ldg(xr + 1), p2 = __ldg(xr + 2);
        float w = __expf(lrelu(p2.y + dd_n + ea_ * ce, 0.2f));
        acc[0] = fmaf(w, p0.x, acc[0]); acc[1] = fmaf(w, p0.y, acc[1]);
        acc[2] = fmaf(w, p0.z, acc[2]); acc[3] = fmaf(w, p0.w, acc[3]);
        acc[4] = fmaf(w, p1.x, acc[4]); acc[5] = fmaf(w, p1.y, acc[5]);
        acc[6] = fmaf(w, p1.z, acc[6]); acc[7] = fmaf(w, p1.w, acc[7]);
        acc[8] = fmaf(w, p2.x, acc[8]);
        wsum += w;
        if (L0) easum += ea_;
    }
    // reduce across the 4-lane sub-warp (xor stays within the group)
#pragma unroll
    for (int o = SWA / 2; o > 0; o >>= 1) {
#pragma unroll
        for (int j = 0; j < F; j++) acc[j] += __shfl_xor_sync(0xFFFFFFFFu, acc[j], o);
        wsum += __shfl_xor_sync(0xFFFFFFFFu, wsum, o);
        if (L0) easum += __shfl_xor_sync(0xFFFFFFFFu, easum, o);
    }
    if (live && lane == 0) {
        float4* ar = reinterpret_cast<float4*>(g_agg + (size_t)n * FP);
        ar[0] = make_float4(acc[0], acc[1], acc[2], acc[3]);
        ar[1] = make_float4(acc[4], acc[5], acc[6], acc[7]);
        ar[2] = make_float4(acc[8], wsum, L0 ? easum : 0.f, 0.f);
    }
}

// --- 4. Finish layer 0 (THREAD per node): self-loop + normalize + b0 +
//        lrelu -> h1; project with W1 -> xpB (carries lattr in slot 11). ----
__global__ void k_fin0(const float* __restrict__ b0,
                       const float* __restrict__ W1,
                       const float* __restrict__ as1, const float* __restrict__ ad1,
                       const float* __restrict__ We0, const float* __restrict__ ae0) {
    __shared__ float sW[F * F];
    __shared__ float sa[2 * F];
    __shared__ float sb[F];
    __shared__ float s_ce;
    int t = threadIdx.x;
    if (t < F * F) sW[t] = W1[t];
    if (t < F) { sa[t] = as1[t]; sb[t] = b0[t]; }
    else if (t < 2 * F) sa[t] = ad1[t - F];
    if (t == 0) {
        float c = 0.f;
#pragma unroll
        for (int j = 0; j < F; j++) c += We0[j] * ae0[j];
        s_ce = c;
    }
    __syncthreads();

    int i = blockIdx.x * blockDim.x + t;
    if (i >= NN) return;

    const float4* ar = reinterpret_cast<const float4*>(g_agg + (size_t)i * FP);
    float4 a0 = ar[0], a1 = ar[1], a2 = ar[2];       // (acc8, wsum, easum, -)
    const float4* pr = reinterpret_cast<const float4*>(g_xpA + (size_t)i * FP);
    float4 p0 = pr[0], p1 = pr[1], p2 = pr[2];       // (xv8, ss, dd, -)
    float acc[F] = {a0.x, a0.y, a0.z, a0.w, a1.x, a1.y, a1.z, a1.w, a2.x};
    float xvn[F] = {p0.x, p0.y, p0.z, p0.w, p1.x, p1.y, p1.z, p1.w, p2.x};
    float deg   = (float)g_cnt[i];
    float lattr = a2.z / fmaxf(deg, 1.f);
    float wself = __expf(lrelu(p2.y + p2.z + lattr * s_ce, 0.2f));
    float inv = 1.f / (a2.y + wself + 1e-16f);
    float hv[F];
#pragma unroll
    for (int k = 0; k < F; k++)
        hv[k] = lrelu(fmaf(wself, xvn[k], acc[k]) * inv + sb[k], 0.01f);
    float4* hr = reinterpret_cast<float4*>(g_h1 + (size_t)i * FP);
    hr[0] = make_float4(hv[0], hv[1], hv[2], hv[3]);
    hr[1] = make_float4(hv[4], hv[5], hv[6], hv[7]);
    hr[2] = make_float4(hv[8], 0.f, 0.f, 0.f);

    float xv[F], ss = 0.f, dd = 0.f;
#pragma unroll
    for (int j = 0; j < F; j++) {
        float a = 0.f;
#pragma unroll
        for (int k = 0; k < F; k++) a += hv[k] * sW[k * F + j];
        xv[j] = a;
        ss += a * sa[j];
        dd += a * sa[F + j];
    }
    float4* xr = reinterpret_cast<float4*>(g_xpB + (size_t)i * FP);
    xr[0] = make_float4(xv[0], xv[1], xv[2], xv[3]);
    xr[1] = make_float4(xv[4], xv[5], xv[6], xv[7]);
    xr[2] = make_float4(xv[8], ss, dd, lattr);
}

// --- 5. Finish layer 1 (THREAD per node): self-loop + normalize + LN +
//        residual + lrelu; precompute edge-head halves us/ud + stats. -------
__global__ void k_post1(const float* __restrict__ b,
                        const float* __restrict__ ng, const float* __restrict__ nb,
                        const float* __restrict__ We1, const float* __restrict__ ae1,
                        const float* __restrict__ g2,
                        const float* __restrict__ etW) {
    __shared__ float sGw[2 * F * F];   // g2[k] * etW[k*F+j]
    __shared__ float s_ce;
    int t = threadIdx.x;
    if (t < 2 * F * F) sGw[t] = g2[t / F] * etW[t];
    if (t == 0) {
        float c = 0.f;
#pragma unroll
        for (int j = 0; j < F; j++) c += We1[j] * ae1[j];
        s_ce = c;
    }
    __syncthreads();

    int i = blockIdx.x * blockDim.x + t;
    if (i >= NN) return;

    const float4* ar = reinterpret_cast<const float4*>(g_agg + (size_t)i * FP);
    float4 a0 = ar[0], a1 = ar[1], a2 = ar[2];       // (acc8, wsum, -, -)
    const float4* pr = reinterpret_cast<const float4*>(g_xpB + (size_t)i * FP);
    float4 p0 = pr[0], p1 = pr[1], p2 = pr[2];       // (xv8, ss, dd, lattr)
    float acc[F] = {a0.x, a0.y, a0.z, a0.w, a1.x, a1.y, a1.z, a1.w, a2.x};
    float xvn[F] = {p0.x, p0.y, p0.z, p0.w, p1.x, p1.y, p1.z, p1.w, p2.x};
    float wself = __expf(lrelu(p2.y + p2.z + p2.w * s_ce, 0.2f));
    float inv = 1.f / (a2.y + wself + 1e-16f);

    float v[F], m = 0.f;
#pragma unroll
    for (int j = 0; j < F; j++) {
        v[j] = fmaf(wself, xvn[j], acc[j]) * inv + b[j];
        m += v[j];
    }
    m *= (1.f / F);
    float var = 0.f;
#pragma unroll
    for (int j = 0; j < F; j++) { float d = v[j] - m; var += d * d; }
    var *= (1.f / F);
    float r = rsqrtf(var + EPS);

    const float4* hr = reinterpret_cast<const float4*>(g_h1 + (size_t)i * FP);
    float4 h0v = hr[0], h1v = hr[1], h2v = hr[2];
    float h1a[F] = {h0v.x, h0v.y, h0v.z, h0v.w, h1v.x, h1v.y, h1v.z, h1v.w, h2v.x};

    float o[F], sum = 0.f, sq = 0.f;
#pragma unroll
    for (int j = 0; j < F; j++) {
        o[j] = lrelu((v[j] - m) * r * ng[j] + nb[j] + h1a[j], 0.01f);
        sum += o[j];
        sq  += o[j] * o[j];
    }

    float us[F], ud[F];
#pragma unroll
    for (int j = 0; j < F; j++) {
        float a = 0.f, bb = 0.f;
#pragma unroll
        for (int k = 0; k < F; k++) {
            a  += o[k] * sGw[k * F + j];
            bb += o[k] * sGw[(F + k) * F + j];
        }
        us[j] = a; ud[j] = bb;
    }
    float4* ur = reinterpret_cast<float4*>(g_us + (size_t)i * FP);
    ur[0] = make_float4(us[0], us[1], us[2], us[3]);
    ur[1] = make_float4(us[4], us[5], us[6], us[7]);
    ur[2] = make_float4(us[8], sum, sq, 0.f);
    float4* vr = reinterpret_cast<float4*>(g_ud + (size_t)i * FP);
    vr[0] = make_float4(ud[0], ud[1], ud[2], ud[3]);
    vr[1] = make_float4(ud[4], ud[5], ud[6], ud[7]);
    vr[2] = make_float4(ud[8], sum, sq, 0.f);
}

// --- 6. Edge head: sub-warp(4) per node, dst row amortized ------------------
__global__ void k_edge_out(const float* __restrict__ g2, const float* __restrict__ b2,
                           const float* __restrict__ etW, const float* __restrict__ etb,
                           const float* __restrict__ fcW, const float* __restrict__ fcb,
                           float* __restrict__ out) {
    __shared__ float sCs[F], sCb[F], sFc[F], sFcb;
    int t = threadIdx.x;
    if (t < F) {
        float cs = 0.f, cb = etb[t];
#pragma unroll
        for (int k = 0; k < 2 * F; k++) {
            cs += g2[k] * etW[k * F + t];
            cb += b2[k] * etW[k * F + t];
        }
        sCs[t] = cs; sCb[t] = cb; sFc[t] = fcW[t];
    }
    if (t == F) sFcb = fcb[0];
    __syncthreads();

    int gsw  = (blockIdx.x * blockDim.x + t) / SWE;
    int lane = t & (SWE - 1);
    if (gsw >= NN) return;                // no shuffles: tail exit is safe
    int n   = gsw;
    int cnt = g_cnt[n];

    const float4* vr = reinterpret_cast<const float4*>(g_ud + (size_t)n * FP);
    float4 v0 = __ldg(vr), v1 = __ldg(vr + 1), v2 = __ldg(vr + 2);

    const int4* bucket = g_bkt + (size_t)n * CAP;
    for (int k = lane; k < cnt; k += SWE) {
        int4 e = __ldg(&bucket[k]);
        float ea = __int_as_float(e.y);
        const float4* ur = reinterpret_cast<const float4*>(g_us + (size_t)e.x * FP);
        float4 u0 = __ldg(ur), u1 = __ldg(ur + 1), u2 = __ldg(ur + 2);

        float m   = (u2.y + v2.y) * (1.f / (2 * F));
        float var = fmaf(-m, m, (u2.z + v2.z) * (1.f / (2 * F)));
        float r   = rsqrtf(var + EPS);
        float u[F] = {u0.x + v0.x, u0.y + v0.y, u0.z + v0.z, u0.w + v0.w,
                      u1.x + v1.x, u1.y + v1.y, u1.z + v1.z, u1.w + v1.w,
                      u2.x + v2.x};
        float eo = sFcb;
#pragma unroll
        for (int j = 0; j < F; j++) {
            float acc = fmaf(r, fmaf(-m, sCs[j], u[j]), sCb[j]);
            eo = fmaf(lrelu(acc, 0.01f), sFc[j], eo);
        }
        out[e.z] = fmaf(2.f, eo, ea);
    }
}

// ---------------------------------------------------------------------------
extern "C" void kernel_launch(void* const* d_in, const int* in_sizes, int n_in,
                              void* d_out, int out_size) {
    const float* x     = (const float*)d_in[0];
    const int*   ei    = (const int*)  d_in[1];
    const float* ea    = (const float*)d_in[2];
    const float* ln1_g = (const float*)d_in[3];
    const float* ln1_b = (const float*)d_in[4];
    const float* W0    = (const float*)d_in[5];
    const float* as0   = (const float*)d_in[6];
    const float* ad0   = (const float*)d_in[7];
    const float* We0   = (const float*)d_in[8];
    const float* ae0   = (const float*)d_in[9];
    const float* b0    = (const float*)d_in[10];
    const float* W1    = (const float*)d_in[11];
    const float* as1   = (const float*)d_in[12];
    const float* ad1   = (const float*)d_in[13];
    const float* We1   = (const float*)d_in[14];
    const float* ae1   = (const float*)d_in[15];
    const float* b1    = (const float*)d_in[16];
    const float* ng1   = (const float*)d_in[17];
    const float* nb1   = (const float*)d_in[18];
    const float* ln2_g = (const float*)d_in[19];
    const float* ln2_b = (const float*)d_in[20];
    const float* et_W  = (const float*)d_in[21];
    const float* et_b  = (const float*)d_in[22];
    const float* fc_W  = (const float*)d_in[23];
    const float* fc_b  = (const float*)d_in[24];
    // att_W / att_b are provably dead (softmax over a single element)

    const int* src = ei;
    const int* dst = ei + NE;
    float* out = (float*)d_out;

    int nbN   = (NN + TPB - 1) / TPB;
    int nbE2  = (NE / 2 + TPB - 1) / TPB;
    int nbAgg = (int)(((size_t)NN * SWA + TPB - 1) / TPB);
    int nbEo  = (int)(((size_t)NN * SWE + TPB - 1) / TPB);

    k_pre<<<nbN, TPB>>>(x, ln1_g, ln1_b, W0, as0, ad0);
    k_scatter<<<nbE2, TPB>>>(src, dst, ea);

    k_agg<true><<<nbAgg, TPB>>>(We0, ae0);                  // GAT layer 0
    k_fin0<<<nbN, TPB>>>(b0, W1, as1, ad1, We0, ae0);

    k_agg<false><<<nbAgg, TPB>>>(We1, ae1);                 // GAT layer 1
    k_post1<<<nbN, TPB>>>(b1, ng1, nb1, We1, ae1, ln2_g, et_W);

    k_edge_out<<<nbEo, TPB>>>(ln2_g, ln2_b, et_W, et_b, fc_W, fc_b, out);
}

// round 17
// speedup vs baseline: 1.0438x; 1.0244x over previous
#include <cuda_runtime.h>
#include <cuda_fp16.h>

// ---------------------------------------------------------------------------
// GNN: ln -> GAT0 -> lrelu -> GAT1 -> ln+res -> lrelu -> edge MLP -> out
// Final attention: softmax over [E,1] == 1.0  =>  out = 2*eo + edge_attr
//
// Round 17: g_us row compressed to 32B (fp16 us9 + fp32 LN stats) so the
// edge head gathers 2 random 16B lines/edge instead of 3; dual-chain ILP
// in the GAT aggregation loops.
// ---------------------------------------------------------------------------

static constexpr int   NN  = 100000;   // nodes
static constexpr int   NE  = 3200000;  // edges
static constexpr int   F   = 9;
static constexpr int   FP  = 12;       // fp32 padded row: 3 x float4
static constexpr int   FPU = 8;        // packed us row: 2 x uint4 (32B)
static constexpr int   CAP = 96;       // per-node bucket capacity (max deg ~70)
static constexpr int   SWA = 4;        // lanes per node in agg kernels
static constexpr int   SWE = 8;        // lanes per node in edge head
static constexpr float EPS = 1e-5f;
static constexpr int   TPB = 256;

// Scratch (device globals; no allocation allowed)
__device__ __align__(16) float g_xpA[NN * FP];   // layer0 proj: [xv9, ss, dd, -]
__device__ __align__(16) float g_xpB[NN * FP];   // layer1 proj: [xv9, ss, dd, lattr]
__device__ __align__(16) float g_agg[NN * FP];   // [acc9, wsum, easum, -]
__device__ __align__(16) float g_h1 [NN * FP];   // residual
__device__ __align__(16) unsigned g_usp[NN * FPU]; // packed: [us01,us23,us45,us67,us8_,sum,sq,-]
__device__ __align__(16) float g_ud [NN * FP];   // [ud9, sum, sumsq, -] (fp32)
__device__ int  g_cnt[NN];                       // bucket cursor == in-degree
__device__ __align__(16) int4 g_bkt[(size_t)NN * CAP];  // (src, ea, eix, 0)

__device__ __forceinline__ float lrelu(float v, float s) {
    return fmaxf(v, s * v);
}
__device__ __forceinline__ unsigned pk2(float a, float b) {
    __half2 h = __floats2half2_rn(a, b);
    return *reinterpret_cast<unsigned*>(&h);
}
__device__ __forceinline__ float2 upk2(unsigned u) {
    __half2 h = *reinterpret_cast<__half2*>(&u);
    return __half22float2(h);
}

// --- 1. LayerNorm x + W0 projection -> xpA; zero cursors -------------------
__global__ void k_pre(const float* __restrict__ x,
                      const float* __restrict__ g, const float* __restrict__ b,
                      const float* __restrict__ W0,
                      const float* __restrict__ as0, const float* __restrict__ ad0) {
    __shared__ float sW[F * F];
    __shared__ float sa[2 * F];
    int t = threadIdx.x;
    if (t < F * F) sW[t] = W0[t];
    if (t < F)          sa[t] = as0[t];
    else if (t < 2 * F) sa[t] = ad0[t - F];
    __syncthreads();

    int i = blockIdx.x * blockDim.x + t;
    if (i >= NN) return;

    float v[F], m = 0.f;
#pragma unroll
    for (int k = 0; k < F; k++) { v[k] = x[i * F + k]; m += v[k]; }
    m *= (1.f / F);
    float var = 0.f;
#pragma unroll
    for (int k = 0; k < F; k++) { float d = v[k] - m; var += d * d; }
    var *= (1.f / F);
    float r = rsqrtf(var + EPS);
    float hv[F];
#pragma unroll
    for (int k = 0; k < F; k++) hv[k] = (v[k] - m) * r * __ldg(&g[k]) + __ldg(&b[k]);

    float xv[F], ss = 0.f, dd = 0.f;
#pragma unroll
    for (int j = 0; j < F; j++) {
        float a = 0.f;
#pragma unroll
        for (int k = 0; k < F; k++) a += hv[k] * sW[k * F + j];
        xv[j] = a;
        ss += a * sa[j];
        dd += a * sa[F + j];
    }
    float4* xr = reinterpret_cast<float4*>(g_xpA + (size_t)i * FP);
    xr[0] = make_float4(xv[0], xv[1], xv[2], xv[3]);
    xr[1] = make_float4(xv[4], xv[5], xv[6], xv[7]);
    xr[2] = make_float4(xv[8], ss, dd, 0.f);
    g_cnt[i] = 0;
}

// --- 2. Build dst-grouped buckets: one 16B store per edge -------------------
__global__ void k_scatter(const int* __restrict__ src, const int* __restrict__ dst,
                          const float* __restrict__ ea) {
    int base = 2 * (blockIdx.x * blockDim.x + threadIdx.x);
    if (base >= NE) return;
    int2   s2 = *reinterpret_cast<const int2*>(src + base);
    int2   d2 = *reinterpret_cast<const int2*>(dst + base);
    float2 a2 = *reinterpret_cast<const float2*>(ea + base);
    int p0 = atomicAdd(&g_cnt[d2.x], 1);
    g_bkt[(size_t)d2.x * CAP + p0] = make_int4(s2.x, __float_as_int(a2.x), base, 0);
    int p1 = atomicAdd(&g_cnt[d2.y], 1);
    g_bkt[(size_t)d2.y * CAP + p1] = make_int4(s2.y, __float_as_int(a2.y), base + 1, 0);
}

// --- 3. GAT aggregation: sub-warp(4) per dst node, dual-chain gather --------
template <bool L0>
__global__ void __launch_bounds__(TPB)
k_agg(const float* __restrict__ We, const float* __restrict__ ae) {
    __shared__ float s_ce;
    if (threadIdx.x == 0) {
        float c = 0.f;
#pragma unroll
        for (int j = 0; j < F; j++) c += We[j] * ae[j];
        s_ce = c;
    }
    __syncthreads();

    int gsw  = (blockIdx.x * blockDim.x + threadIdx.x) / SWA;
    int lane = threadIdx.x & (SWA - 1);
    bool live = (gsw < NN);
    int n = live ? gsw : (NN - 1);        // clamp: keep full warp for shuffles
    int cnt = g_cnt[n];
    const float* __restrict__ xp = L0 ? g_xpA : g_xpB;
    float dd_n = __ldg(&xp[(size_t)n * FP + 10]);
    float ce = s_ce;

    float acc[F] = {0.f, 0.f, 0.f, 0.f, 0.f, 0.f, 0.f, 0.f, 0.f};
    float wsum = 0.f, easum = 0.f;
    const int4* bucket = g_bkt + (size_t)n * CAP;

    int k = lane;
    // dual-chain main loop: two independent gather->exp->fma chains in flight
    for (; k + SWA < cnt; k += 2 * SWA) {
        int4 e0 = __ldg(&bucket[k]);
        int4 e1 = __ldg(&bucket[k + SWA]);
        const float4* xr0 = reinterpret_cast<const float4*>(xp + (size_t)e0.x * FP);
        const float4* xr1 = reinterpret_cast<const float4*>(xp + (size_t)e1.x * FP);
        float4 a0 = __ldg(xr0), a1 = __ldg(xr0 + 1), a2 = __ldg(xr0 + 2);
        float4 b0 = __ldg(xr1), b1 = __ldg(xr1 + 1), b2 = __ldg(xr1 + 2);
        float eaa = __int_as_float(e0.y);
        float eab = __int_as_float(e1.y);
        float wa = __expf(lrelu(a2.y + dd_n + eaa * ce, 0.2f));
        float wb = __expf(lrelu(b2.y + dd_n + eab * ce, 0.2f));
        acc[0] = fmaf(wa, a0.x, acc[0]); acc[1] = fmaf(wa, a0.y, acc[1]);
        acc[2] = fmaf(wa, a0.z, acc[2]); acc[3] = fmaf(wa, a0.w, acc[3]);
        acc[4] = fmaf(wa, a1.x, acc[4]); acc[5] = fmaf(wa, a1.y, acc[5]);
        acc[6] = fmaf(wa, a1.z, acc[6]); acc[7] = fmaf(wa, a1.w, acc[7]);
        acc[8] = fmaf(wa, a2.x, acc[8]);
        acc[0] = fmaf(wb, b0.x, acc[0]); acc[1] = fmaf(wb, b0.y, acc[1]);
        acc[2] = fmaf(wb, b0.z, acc[2]); acc[3] = fmaf(wb, b0.w, acc[3]);
        acc[4] = fmaf(wb, b1.x, acc[4]); acc[5] = fmaf(wb, b1.y, acc[5]);
        acc[6] = fmaf(wb, b1.z, acc[6]); acc[7] = fmaf(wb, b1.w, acc[7]);
        acc[8] = fmaf(wb, b2.x, acc[8]);
        wsum += wa + wb;
        if (L0) easum += eaa + eab;
    }
    if (k < cnt) {
        int4 e0 = __ldg(&bucket[k]);
        const float4* xr0 = reinterpret_cast<const float4*>(xp + (size_t)e0.x * FP);
        float4 a0 = __ldg(xr0), a1 = __ldg(xr0 + 1), a2 = __ldg(xr0 + 2);
        float eaa = __int_as_float(e0.y);
        float wa = __expf(lrelu(a2.y + dd_n + eaa * ce, 0.2f));
        acc[0] = fmaf(wa, a0.x, acc[0]); acc[1] = fmaf(wa, a0.y, acc[1]);
        acc[2] = fmaf(wa, a0.z, acc[2]); acc[3] = fmaf(wa, a0.w, acc[3]);
        acc[4] = fmaf(wa, a1.x, acc[4]); acc[5] = fmaf(wa, a1.y, acc[5]);
        acc[6] = fmaf(wa, a1.z, acc[6]); acc[7] = fmaf(wa, a1.w, acc[7]);
        acc[8] = fmaf(wa, a2.x, acc[8]);
        wsum += wa;
        if (L0) easum += eaa;
    }

    // reduce across the 4-lane sub-warp (xor stays within the group)
#pragma unroll
    for (int o = SWA / 2; o > 0; o >>= 1) {
#pragma unroll
        for (int j = 0; j < F; j++) acc[j] += __shfl_xor_sync(0xFFFFFFFFu, acc[j], o);
        wsum += __shfl_xor_sync(0xFFFFFFFFu, wsum, o);
        if (L0) easum += __shfl_xor_sync(0xFFFFFFFFu, easum, o);
    }
    if (live && lane == 0) {
        float4* ar = reinterpret_cast<float4*>(g_agg + (size_t)n * FP);
        ar[0] = make_float4(acc[0], acc[1], acc[2], acc[3]);
        ar[1] = make_float4(acc[4], acc[5], acc[6], acc[7]);
        ar[2] = make_float4(acc[8], wsum, L0 ? easum : 0.f, 0.f);
    }
}

// --- 4. Finish layer 0 (THREAD per node): self-loop + normalize + b0 +
//        lrelu -> h1; project with W1 -> xpB (carries lattr in slot 11). ----
__global__ void k_fin0(const float* __restrict__ b0,
                       const float* __restrict__ W1,
                       const float* __restrict__ as1, const float* __restrict__ ad1,
                       const float* __restrict__ We0, const float* __restrict__ ae0) {
    __shared__ float sW[F * F];
    __shared__ float sa[2 * F];
    __shared__ float sb[F];
    __shared__ float s_ce;
    int t = threadIdx.x;
    if (t < F * F) sW[t] = W1[t];
    if (t < F) { sa[t] = as1[t]; sb[t] = b0[t]; }
    else if (t < 2 * F) sa[t] = ad1[t - F];
    if (t == 0) {
        float c = 0.f;
#pragma unroll
        for (int j = 0; j < F; j++) c += We0[j] * ae0[j];
        s_ce = c;
    }
    __syncthreads();

    int i = blockIdx.x * blockDim.x + t;
    if (i >= NN) return;

    const float4* ar = reinterpret_cast<const float4*>(g_agg + (size_t)i * FP);
    float4 a0 = ar[0], a1 = ar[1], a2 = ar[2];       // (acc8, wsum, easum, -)
    const float4* pr = reinterpret_cast<const float4*>(g_xpA + (size_t)i * FP);
    float4 p0 = pr[0], p1 = pr[1], p2 = pr[2];       // (xv8, ss, dd, -)
    float acc[F] = {a0.x, a0.y, a0.z, a0.w, a1.x, a1.y, a1.z, a1.w, a2.x};
    float xvn[F] = {p0.x, p0.y, p0.z, p0.w, p1.x, p1.y, p1.z, p1.w, p2.x};
    float deg   = (float)g_cnt[i];
    float lattr = a2.z / fmaxf(deg, 1.f);
    float wself = __expf(lrelu(p2.y + p2.z + lattr * s_ce, 0.2f));
    float inv = 1.f / (a2.y + wself + 1e-16f);
    float hv[F];
#pragma unroll
    for (int k = 0; k < F; k++)
        hv[k] = lrelu(fmaf(wself, xvn[k], acc[k]) * inv + sb[k], 0.01f);
    float4* hr = reinterpret_cast<float4*>(g_h1 + (size_t)i * FP);
    hr[0] = make_float4(hv[0], hv[1], hv[2], hv[3]);
    hr[1] = make_float4(hv[4], hv[5], hv[6], hv[7]);
    hr[2] = make_float4(hv[8], 0.f, 0.f, 0.f);

    float xv[F], ss = 0.f, dd = 0.f;
#pragma unroll
    for (int j = 0; j < F; j++) {
        float a = 0.f;
#pragma unroll
        for (int k = 0; k < F; k++) a += hv[k] * sW[k * F + j];
        xv[j] = a;
        ss += a * sa[j];
        dd += a * sa[F + j];
    }
    float4* xr = reinterpret_cast<float4*>(g_xpB + (size_t)i * FP);
    xr[0] = make_float4(xv[0], xv[1], xv[2], xv[3]);
    xr[1] = make_float4(xv[4], xv[5], xv[6], xv[7]);
    xr[2] = make_float4(xv[8], ss, dd, lattr);
}

// --- 5. Finish layer 1 (THREAD per node): self-loop + normalize + LN +
//        residual + lrelu; precompute us (packed fp16) / ud (fp32) + stats. --
__global__ void k_post1(const float* __restrict__ b,
                        const float* __restrict__ ng, const float* __restrict__ nb,
                        const float* __restrict__ We1, const float* __restrict__ ae1,
                        const float* __restrict__ g2,
                        const float* __restrict__ etW) {
    __shared__ float sGw[2 * F * F];   // g2[k] * etW[k*F+j]
    __shared__ float s_ce;
    int t = threadIdx.x;
    if (t < 2 * F * F) sGw[t] = g2[t / F] * etW[t];
    if (t == 0) {
        float c = 0.f;
#pragma unroll
        for (int j = 0; j < F; j++) c += We1[j] * ae1[j];
        s_ce = c;
    }
    __syncthreads();

    int i = blockIdx.x * blockDim.x + t;
    if (i >= NN) return;

    const float4* ar = reinterpret_cast<const float4*>(g_agg + (size_t)i * FP);
    float4 a0 = ar[0], a1 = ar[1], a2 = ar[2];       // (acc8, wsum, -, -)
    const float4* pr = reinterpret_cast<const float4*>(g_xpB + (size_t)i * FP);
    float4 p0 = pr[0], p1 = pr[1], p2 = pr[2];       // (xv8, ss, dd, lattr)
    float acc[F] = {a0.x, a0.y, a0.z, a0.w, a1.x, a1.y, a1.z, a1.w, a2.x};
    float xvn[F] = {p0.x, p0.y, p0.z, p0.w, p1.x, p1.y, p1.z, p1.w, p2.x};
    float wself = __expf(lrelu(p2.y + p2.z + p2.w * s_ce, 0.2f));
    float inv = 1.f / (a2.y + wself + 1e-16f);

    float v[F], m = 0.f;
#pragma unroll
    for (int j = 0; j < F; j++) {
        v[j] = fmaf(wself, xvn[j], acc[j]) * inv + b[j];
        m += v[j];
    }
    m *= (1.f / F);
    float var = 0.f;
#pragma unroll
    for (int j = 0; j < F; j++) { float d = v[j] - m; var += d * d; }
    var *= (1.f / F);
    float r = rsqrtf(var + EPS);

    const float4* hr = reinterpret_cast<const float4*>(g_h1 + (size_t)i * FP);
    float4 h0v = hr[0], h1v = hr[1], h2v = hr[2];
    float h1a[F] = {h0v.x, h0v.y, h0v.z, h0v.w, h1v.x, h1v.y, h1v.z, h1v.w, h2v.x};

    float o[F], sum = 0.f, sq = 0.f;
#pragma unroll
    for (int j = 0; j < F; j++) {
        o[j] = lrelu((v[j] - m) * r * ng[j] + nb[j] + h1a[j], 0.01f);
        sum += o[j];
        sq  += o[j] * o[j];
    }

    float us[F], ud[F];
#pragma unroll
    for (int j = 0; j < F; j++) {
        float a = 0.f, bb = 0.f;
#pragma unroll
        for (int k = 0; k < F; k++) {
            a  += o[k] * sGw[k * F + j];
            bb += o[k] * sGw[(F + k) * F + j];
        }
        us[j] = a; ud[j] = bb;
    }
    // src half: packed fp16 row (32B) — gathered per edge
    uint4* ur = reinterpret_cast<uint4*>(g_usp + (size_t)i * FPU);
    ur[0] = make_uint4(pk2(us[0], us[1]), pk2(us[2], us[3]),
                       pk2(us[4], us[5]), pk2(us[6], us[7]));
    ur[1] = make_uint4(pk2(us[8], 0.f), __float_as_uint(sum),
                       __float_as_uint(sq), 0u);
    // dst half: fp32 (broadcast once per node in the edge head)
    float4* vr = reinterpret_cast<float4*>(g_ud + (size_t)i * FP);
    vr[0] = make_float4(ud[0], ud[1], ud[2], ud[3]);
    vr[1] = make_float4(ud[4], ud[5], ud[6], ud[7]);
    vr[2] = make_float4(ud[8], sum, sq, 0.f);
}

// --- 6. Edge head: sub-warp(8) per node; 2 random 16B gathers per edge -----
__global__ void __launch_bounds__(TPB)
k_edge_out(const float* __restrict__ g2, const float* __restrict__ b2,
           const float* __restrict__ etW, const float* __restrict__ etb,
           const float* __restrict__ fcW, const float* __restrict__ fcb,
           float* __restrict__ out) {
    __shared__ float sCs[F], sCb[F], sFc[F], sFcb;
    int t = threadIdx.x;
    if (t < F) {
        float cs = 0.f, cb = etb[t];
#pragma unroll
        for (int k = 0; k < 2 * F; k++) {
            cs += g2[k] * etW[k * F + t];
            cb += b2[k] * etW[k * F + t];
        }
        sCs[t] = cs; sCb[t] = cb; sFc[t] = fcW[t];
    }
    if (t == F) sFcb = fcb[0];
    __syncthreads();

    int gsw  = (blockIdx.x * blockDim.x + t) / SWE;
    int lane = t & (SWE - 1);
    if (gsw >= NN) return;                // grid exact: never taken
    int n   = gsw;
    int cnt = g_cnt[n];

    const float4* vr = reinterpret_cast<const float4*>(g_ud + (size_t)n * FP);
    float4 v0 = __ldg(vr), v1 = __ldg(vr + 1), v2 = __ldg(vr + 2);

    const int4* bucket = g_bkt + (size_t)n * CAP;
    for (int k = lane; k < cnt; k += SWE) {
        int4 e = __ldg(&bucket[k]);
        float ea = __int_as_float(e.y);
        const uint4* ur = reinterpret_cast<const uint4*>(g_usp + (size_t)e.x * FPU);
        uint4 q0 = __ldg(ur), q1 = __ldg(ur + 1);
        float2 u01 = upk2(q0.x), u23 = upk2(q0.y);
        float2 u45 = upk2(q0.z), u67 = upk2(q0.w);
        float2 u8_ = upk2(q1.x);
        float sum_s = __uint_as_float(q1.y);
        float sq_s  = __uint_as_float(q1.z);

        float m   = (sum_s + v2.y) * (1.f / (2 * F));
        float var = fmaf(-m, m, (sq_s + v2.z) * (1.f / (2 * F)));
        float r   = rsqrtf(var + EPS);
        float u[F] = {u01.x + v0.x, u01.y + v0.y, u23.x + v0.z, u23.y + v0.w,
                      u45.x + v1.x, u45.y + v1.y, u67.x + v1.z, u67.y + v1.w,
                      u8_.x + v2.x};
        float eo = sFcb;
#pragma unroll
        for (int j = 0; j < F; j++) {
            float acc = fmaf(r, fmaf(-m, sCs[j], u[j]), sCb[j]);
            eo = fmaf(lrelu(acc, 0.01f), sFc[j], eo);
        }
        out[e.z] = fmaf(2.f, eo, ea);
    }
}

// ---------------------------------------------------------------------------
extern "C" void kernel_launch(void* const* d_in, const int* in_sizes, int n_in,
                              void* d_out, int out_size) {
    const float* x     = (const float*)d_in[0];
    const int*   ei    = (const int*)  d_in[1];
    const float* ea    = (const float*)d_in[2];
    const float* ln1_g = (const float*)d_in[3];
    const float* ln1_b = (const float*)d_in[4];
    const float* W0    = (const float*)d_in[5];
    const float* as0   = (const float*)d_in[6];
    const float* ad0   = (const float*)d_in[7];
    const float* We0   = (const float*)d_in[8];
    const float* ae0   = (const float*)d_in[9];
    const float* b0    = (const float*)d_in[10];
    const float* W1    = (const float*)d_in[11];
    const float* as1   = (const float*)d_in[12];
    const float* ad1   = (const float*)d_in[13];
    const float* We1   = (const float*)d_in[14];
    const float* ae1   = (const float*)d_in[15];
    const float* b1    = (const float*)d_in[16];
    const float* ng1   = (const float*)d_in[17];
    const float* nb1   = (const float*)d_in[18];
    const float* ln2_g = (const float*)d_in[19];
    const float* ln2_b = (const float*)d_in[20];
    const float* et_W  = (const float*)d_in[21];
    const float* et_b  = (const float*)d_in[22];
    const float* fc_W  = (const float*)d_in[23];
    const float* fc_b  = (const float*)d_in[24];
    // att_W / att_b are provably dead (softmax over a single element)

    const int* src = ei;
    const int* dst = ei + NE;
    float* out = (float*)d_out;

    int nbN   = (NN + TPB - 1) / TPB;
    int nbE2  = (NE / 2 + TPB - 1) / TPB;
    int nbAgg = (int)(((size_t)NN * SWA + TPB - 1) / TPB);
    int nbEo  = (int)(((size_t)NN * SWE + TPB - 1) / TPB);

    k_pre<<<nbN, TPB>>>(x, ln1_g, ln1_b, W0, as0, ad0);
    k_scatter<<<nbE2, TPB>>>(src, dst, ea);

    k_agg<true><<<nbAgg, TPB>>>(We0, ae0);                  // GAT layer 0
    k_fin0<<<nbN, TPB>>>(b0, W1, as1, ad1, We0, ae0);

    k_agg<false><<<nbAgg, TPB>>>(We1, ae1);                 // GAT layer 1
    k_post1<<<nbN, TPB>>>(b1, ng1, nb1, We1, ae1, ln2_g, et_W);

    k_edge_out<<<nbEo, TPB>>>(ln2_g, ln2_b, et_W, et_b, fc_W, fc_b, out);
}